// round 14
// baseline (speedup 1.0000x reference)
#include <cuda_runtime.h>
#include <cstdint>

#define BATCH 32
#define CI    128
#define CO    256
#define HH    56
#define WW    56
#define HP    58
#define WP    58
#define KTOT2 768           // 6 groups x 128 ic
#define NCHUNKS 24          // KTOT2 / 32
#define HW    (HH * WW)     // 3136

#define STAGES      3
#define STAGE_BYTES 24576       // A 16KB (128 rows) + B 8KB (64 rows)
#define OFF_B_STAGE 16384
#define OFF_BIAS    (STAGES * STAGE_BYTES)      // 73728
#define SMEM_TOTAL  (STAGES * STAGE_BYTES + 256)

__device__ float g_xpad[BATCH * HP * WP * CI];   // NHWC, zero halo, full fp32
__device__ float g_vsum[BATCH * HH * WP * CI];   // vertical 3-sum, tf32-rounded
__device__ float g_hsum[BATCH * HP * WW * CI];   // horizontal 3-sum, tf32-rounded
__device__ float g_weff[CO * KTOT2];             // [oc][g*128+ic] = krow|kcol, tf32

__device__ __forceinline__ uint32_t smem_u32(const void* p) {
    uint32_t a;
    asm("{ .reg .u64 t; cvta.to.shared.u64 t, %1; cvt.u32.u64 %0, t; }" : "=r"(a) : "l"(p));
    return a;
}
__device__ __forceinline__ float tf32r(float v) {
    uint32_t r;
    asm("cvt.rna.tf32.f32 %0, %1;" : "=r"(r) : "f"(v));
    return __uint_as_float(r);
}
__device__ __forceinline__ void mma_tf32(float* d, const uint32_t* a, uint32_t b0, uint32_t b1) {
    asm volatile(
        "mma.sync.aligned.m16n8k8.row.col.f32.tf32.tf32.f32 "
        "{%0,%1,%2,%3}, {%4,%5,%6,%7}, {%8,%9}, {%0,%1,%2,%3};"
        : "+f"(d[0]), "+f"(d[1]), "+f"(d[2]), "+f"(d[3])
        : "r"(a[0]), "r"(a[1]), "r"(a[2]), "r"(a[3]), "r"(b0), "r"(b1));
}
__device__ __forceinline__ void ldsm4(uint32_t* r, uint32_t addr) {
    asm volatile("ldmatrix.sync.aligned.m8n8.x4.shared.b16 {%0,%1,%2,%3}, [%4];"
        : "=r"(r[0]), "=r"(r[1]), "=r"(r[2]), "=r"(r[3]) : "r"(addr));
}
__device__ __forceinline__ void cp16(uint32_t saddr, const float* g) {
    asm volatile("cp.async.cg.shared.global [%0], [%1], 16;"
        :: "r"(saddr), "l"(__cvta_generic_to_global(g)) : "memory");
}
#define CP_COMMIT() asm volatile("cp.async.commit_group;" ::: "memory")
#define CP_WAIT1()  asm volatile("cp.async.wait_group 1;" ::: "memory")

// ---------------------------------------------------------------------------
// Prep kernels
// ---------------------------------------------------------------------------
// Zero only the halo of xpad (rows hp=0,57; cols wp=0,57). grid (228, BATCH), block 32.
__global__ void zero_halo_kernel() {
    const int p = blockIdx.x, b = blockIdx.y;
    int hp, wp;
    if      (p < 58)  { hp = 0;            wp = p;        }
    else if (p < 116) { hp = 57;           wp = p - 58;   }
    else if (p < 172) { hp = p - 116 + 1;  wp = 0;        }
    else              { hp = p - 172 + 1;  wp = 57;       }
    float4* d = (float4*)&g_xpad[((size_t)(b * HP + hp) * WP + wp) * CI];
    d[threadIdx.x] = make_float4(0.f, 0.f, 0.f, 0.f);
}

// NCHW -> padded NHWC (full fp32; rounding happens after the 3-sums)
__global__ void transpose_kernel(const float* __restrict__ x) {
    __shared__ float t[32][57];
    const int h = blockIdx.x, icb = blockIdx.y, b = blockIdx.z, tid = threadIdx.x;
    for (int i = tid; i < 32 * 56; i += 256) {
        int ic_l = i / 56, w = i % 56;
        t[ic_l][w] = x[((size_t)(b * CI + icb * 32 + ic_l) * HH + h) * WW + w];
    }
    __syncthreads();
    for (int i = tid; i < 56 * 32; i += 256) {
        int w = i / 32, ic_l = i % 32;
        g_xpad[((size_t)(b * HP + h + 1) * WP + (w + 1)) * CI + icb * 32 + ic_l] = t[ic_l][w];
    }
}

// vsum[b][h][wp][ic] = sum_{d=0..2} xpad[b][h+d][wp][ic], tf32-rounded
__global__ void vsum_kernel() {
    const int h = blockIdx.x, b = blockIdx.y;
    const float4* r0 = (const float4*)&g_xpad[((size_t)(b * HP + h    ) * WP) * CI];
    const float4* r1 = (const float4*)&g_xpad[((size_t)(b * HP + h + 1) * WP) * CI];
    const float4* r2 = (const float4*)&g_xpad[((size_t)(b * HP + h + 2) * WP) * CI];
    float4* dst = (float4*)&g_vsum[((size_t)(b * HH + h) * WP) * CI];
    for (int i = threadIdx.x; i < WP * CI / 4; i += blockDim.x) {
        float4 a = r0[i], c = r1[i], e = r2[i];
        float4 o;
        o.x = tf32r(a.x + c.x + e.x);
        o.y = tf32r(a.y + c.y + e.y);
        o.z = tf32r(a.z + c.z + e.z);
        o.w = tf32r(a.w + c.w + e.w);
        dst[i] = o;
    }
}

// hsum[b][hp][w][ic] = sum_{d=0..2} xpad[b][hp][w+d][ic], tf32-rounded
__global__ void hsum_kernel() {
    const int hp = blockIdx.x, b = blockIdx.y;
    const float4* row = (const float4*)&g_xpad[((size_t)(b * HP + hp) * WP) * CI];
    float4* dst = (float4*)&g_hsum[((size_t)(b * HP + hp) * WW) * CI];
    const int C4 = CI / 4;
    for (int i = threadIdx.x; i < WW * C4; i += blockDim.x) {
        int w = i / C4, q = i % C4;
        float4 a = row[(w    ) * C4 + q];
        float4 c = row[(w + 1) * C4 + q];
        float4 e = row[(w + 2) * C4 + q];
        float4 o;
        o.x = tf32r(a.x + c.x + e.x);
        o.y = tf32r(a.y + c.y + e.y);
        o.z = tf32r(a.z + c.z + e.z);
        o.w = tf32r(a.w + c.w + e.w);
        dst[i] = o;
    }
}

// weff[o][g*128+i]: g 0..2 -> krow[o,i,s=g] (pairs vsum); g 3..5 -> kcol[o,i,r=g-3] (pairs hsum)
__global__ void weff_kernel(const float* __restrict__ w) {
    int idx = blockIdx.x * blockDim.x + threadIdx.x;
    if (idx >= CO * CI) return;
    int o = idx / CI, i = idx % CI;
    const float* wp = w + (size_t)(o * CI + i) * 9;
    float v[9];
#pragma unroll
    for (int t = 0; t < 9; ++t) v[t] = wp[t];
#pragma unroll
    for (int j = 0; j < 3; ++j) {
        float krow = v[j * 3 + 0] + v[j * 3 + 1] + v[j * 3 + 2];   // row j over columns
        float kcol = v[0 * 3 + j] + v[1 * 3 + j] + v[2 * 3 + j];   // column j over rows
        g_weff[(size_t)o * KTOT2 + (j    ) * 128 + i] = tf32r(krow);
        g_weff[(size_t)o * KTOT2 + (j + 3) * 128 + i] = tf32r(kcol);
    }
}

// ---------------------------------------------------------------------------
// Main kernel: CTA tile 128x64, 8 warps of 32x32, 3 CTAs/SM, frag ping-pong
// grid = (784, 4), block = 256
// ---------------------------------------------------------------------------
__global__ __launch_bounds__(256, 3)
void conv_mma_kernel(const float* __restrict__ bias, float* __restrict__ y) {
    extern __shared__ char smem[];
    const uint32_t sb = smem_u32(smem);

    const int tid  = threadIdx.x;
    const int lane = tid & 31;
    const int wid  = tid >> 5;
    const int m0   = blockIdx.x * 128;
    const int n0   = blockIdx.y * 64;

    // ---- A staging identity: row rloc (0..127), 4 segments starting at 4*(tid>>7) ----
    const int rloc  = tid & 127;
    const int aseg0 = (tid >> 7) * 4;
    const int m_g   = m0 + rloc;
    const int b_s   = m_g / HW;
    const int hw_s  = m_g % HW;
    const int h_s   = hw_s / WW;
    const int w_s   = hw_s % WW;
    const float* vbase = g_vsum + (((size_t)(b_s * HH + h_s) * WP) + w_s) * CI;
    const float* hbase = g_hsum + (((size_t)(b_s * HP + h_s) * WW) + w_s) * CI;
    const int rpA = rloc & 7;

    // ---- B staging identity: row brow (0..63), 2 segments starting at 2*(tid>>6) ----
    const int brow  = tid & 63;
    const int bseg0 = (tid >> 6) * 2;
    const float* bSrc0 = g_weff + (size_t)(n0 + brow) * KTOT2;
    const int rpB = brow & 7;

    if (tid < 64) ((float*)(smem + OFF_BIAS))[tid] = bias[n0 + tid];

    // ---- ldmatrix lane geometry ----
    const int t   = lane >> 3;
    const int rin = lane & 7;
    const int m0w = (wid & 3) * 32;
    const int n0w = (wid >> 2) * 32;
    const int thalfA = t >> 1;      // A seg sub-index
    uint32_t offA[2]; int permA[2];
#pragma unroll
    for (int mt = 0; mt < 2; ++mt) {
        int row = m0w + mt * 16 + (t & 1) * 8 + rin;
        offA[mt] = (uint32_t)row * 128;
        permA[mt] = row & 7;
    }
    const int segBoff = t & 1;
    uint32_t offB[2]; int permB[2];
#pragma unroll
    for (int p = 0; p < 2; ++p) {
        int row = n0w + p * 16 + (t >> 1) * 8 + rin;
        offB[p] = (uint32_t)row * 128 + OFF_B_STAGE;
        permB[p] = row & 7;
    }

    float acc[2][4][4];
#pragma unroll
    for (int mt = 0; mt < 2; ++mt)
#pragma unroll
        for (int nt = 0; nt < 4; ++nt)
#pragma unroll
            for (int e = 0; e < 4; ++e) acc[mt][nt][e] = 0.f;

    // ---- staging helper: group g = c>>2 selects vsum (g<3) or hsum (g>=3) ----
    auto stage = [&](int c) {
        const int st  = c % STAGES;
        const int g   = c >> 2;
        const int icq = c & 3;
        const float* ap = (g < 3)
            ? vbase + (size_t)g * CI + icq * 32
            : hbase + (size_t)(g - 3) * WW * CI + icq * 32;
        const float* bp = bSrc0 + c * 32;
        const uint32_t sA = sb + st * STAGE_BYTES + (uint32_t)rloc * 128;
        const uint32_t sB = sb + st * STAGE_BYTES + OFF_B_STAGE + (uint32_t)brow * 128;
#pragma unroll
        for (int j = 0; j < 4; ++j) {
            const int s = aseg0 + j;
            cp16(sA + (uint32_t)((s ^ rpA) << 4), ap + s * 4);
        }
#pragma unroll
        for (int j = 0; j < 2; ++j) {
            const int s = bseg0 + j;
            cp16(sB + (uint32_t)((s ^ rpB) << 4), bp + s * 4);
        }
    };

    stage(0); CP_COMMIT();
    stage(1); CP_COMMIT();

    uint32_t af[2][8], bf[2][8];

    auto load_frags = [&](uint32_t stBase, int ks, int buf) {
#pragma unroll
        for (int mt = 0; mt < 2; ++mt)
            ldsm4(&af[buf][mt * 4],
                  stBase + offA[mt] + (uint32_t)(((2 * ks + thalfA) ^ permA[mt]) << 4));
#pragma unroll
        for (int p = 0; p < 2; ++p)
            ldsm4(&bf[buf][p * 4],
                  stBase + offB[p] + (uint32_t)(((2 * ks + segBoff) ^ permB[p]) << 4));
    };

    for (int c = 0; c < NCHUNKS; ++c) {
        CP_WAIT1();
        __syncthreads();

        if (c + 2 < NCHUNKS) stage(c + 2);
        CP_COMMIT();

        const uint32_t stBase = sb + (c % STAGES) * STAGE_BYTES;
        load_frags(stBase, 0, 0);
#pragma unroll
        for (int ks = 0; ks < 4; ++ks) {
            const int cur = ks & 1;
            if (ks < 3) load_frags(stBase, ks + 1, cur ^ 1);
#pragma unroll
            for (int mt = 0; mt < 2; ++mt)
#pragma unroll
                for (int nt = 0; nt < 4; ++nt)
                    mma_tf32(acc[mt][nt], &af[cur][mt * 4],
                             bf[cur][(nt >> 1) * 4 + (nt & 1) * 2],
                             bf[cur][(nt >> 1) * 4 + (nt & 1) * 2 + 1]);
        }
    }

    // ---- epilogue: scatter to NCHW + bias ----
    const int qrow = lane >> 2;
    const int qcol = lane & 3;
    const float* sbias = (const float*)(smem + OFF_BIAS);
#pragma unroll
    for (int mt = 0; mt < 2; ++mt) {
#pragma unroll
        for (int rr = 0; rr < 2; ++rr) {
            const int mg = m0 + m0w + mt * 16 + qrow + rr * 8;
            const int b  = mg / HW;
            const int hw = mg % HW;
            float* yb = y + (size_t)b * CO * HW + hw;
#pragma unroll
            for (int nt = 0; nt < 4; ++nt) {
                const int ocl = n0w + nt * 8 + 2 * qcol;
                const int oc  = n0 + ocl;
                yb[(size_t)(oc    ) * HW] = acc[mt][nt][rr * 2 + 0] + sbias[ocl];
                yb[(size_t)(oc + 1) * HW] = acc[mt][nt][rr * 2 + 1] + sbias[ocl + 1];
            }
        }
    }
}

// ---------------------------------------------------------------------------
extern "C" void kernel_launch(void* const* d_in, const int* in_sizes, int n_in,
                              void* d_out, int out_size) {
    const float* x    = (const float*)d_in[0];
    const float* w    = (const float*)d_in[1];
    const float* bias = (const float*)d_in[2];
    float* y = (float*)d_out;

    zero_halo_kernel<<<dim3(228, BATCH), 32>>>();
    transpose_kernel<<<dim3(HH, CI / 32, BATCH), 256>>>(x);
    vsum_kernel<<<dim3(HH, BATCH), 256>>>();
    hsum_kernel<<<dim3(HP, BATCH), 256>>>();
    weff_kernel<<<(CO * CI + 255) / 256, 256>>>(w);

    cudaFuncSetAttribute(conv_mma_kernel,
                         cudaFuncAttributeMaxDynamicSharedMemorySize, SMEM_TOTAL);
    dim3 grid(BATCH * HW / 128, CO / 64);
    conv_mma_kernel<<<grid, 256, SMEM_TOTAL>>>(bias, y);
}

// round 15
// speedup vs baseline: 1.1607x; 1.1607x over previous
#include <cuda_runtime.h>
#include <cstdint>

#define BATCH 32
#define CI    128
#define CO    256
#define HH    56
#define WW    56
#define HP    58
#define WP    58
#define KTOT2 768           // 6 groups x 128 ic
#define NCHUNKS 24          // KTOT2 / 32
#define HW    (HH * WW)     // 3136

#define STAGES      4
#define STAGE_BYTES 49152       // A 16KB (128 rows) + B 32KB (256 rows)
#define OFF_B_STAGE 16384
#define OFF_BIAS    (STAGES * STAGE_BYTES)      // 196608
#define SMEM_TOTAL  (STAGES * STAGE_BYTES + CO * 4)

__device__ float g_xpad[BATCH * HP * WP * CI];   // NHWC, zero halo, full fp32
__device__ float g_vsum[BATCH * HH * WP * CI];   // vertical 3-sum, tf32-rounded
__device__ float g_hsum[BATCH * HP * WW * CI];   // horizontal 3-sum, tf32-rounded
__device__ float g_weff[CO * KTOT2];             // [oc][g*128+ic] = krow|kcol, tf32

__device__ __forceinline__ uint32_t smem_u32(const void* p) {
    uint32_t a;
    asm("{ .reg .u64 t; cvta.to.shared.u64 t, %1; cvt.u32.u64 %0, t; }" : "=r"(a) : "l"(p));
    return a;
}
__device__ __forceinline__ float tf32r(float v) {
    uint32_t r;
    asm("cvt.rna.tf32.f32 %0, %1;" : "=r"(r) : "f"(v));
    return __uint_as_float(r);
}
__device__ __forceinline__ void mma_tf32(float* d, const uint32_t* a, uint32_t b0, uint32_t b1) {
    asm volatile(
        "mma.sync.aligned.m16n8k8.row.col.f32.tf32.tf32.f32 "
        "{%0,%1,%2,%3}, {%4,%5,%6,%7}, {%8,%9}, {%0,%1,%2,%3};"
        : "+f"(d[0]), "+f"(d[1]), "+f"(d[2]), "+f"(d[3])
        : "r"(a[0]), "r"(a[1]), "r"(a[2]), "r"(a[3]), "r"(b0), "r"(b1));
}
__device__ __forceinline__ void ldsm4(uint32_t* r, uint32_t addr) {
    asm volatile("ldmatrix.sync.aligned.m8n8.x4.shared.b16 {%0,%1,%2,%3}, [%4];"
        : "=r"(r[0]), "=r"(r[1]), "=r"(r[2]), "=r"(r[3]) : "r"(addr));
}
__device__ __forceinline__ void cp16(uint32_t saddr, const float* g) {
    asm volatile("cp.async.cg.shared.global [%0], [%1], 16;"
        :: "r"(saddr), "l"(__cvta_generic_to_global(g)) : "memory");
}
#define CP_COMMIT() asm volatile("cp.async.commit_group;" ::: "memory")
#define CP_WAIT2()  asm volatile("cp.async.wait_group 2;" ::: "memory")

// ---------------------------------------------------------------------------
// Prep kernels
// ---------------------------------------------------------------------------
// Zero only the halo of xpad (rows hp=0,57; cols wp=0,57). grid (228, BATCH), block 32.
__global__ void zero_halo_kernel() {
    const int p = blockIdx.x, b = blockIdx.y;
    int hp, wp;
    if      (p < 58)  { hp = 0;            wp = p;        }
    else if (p < 116) { hp = 57;           wp = p - 58;   }
    else if (p < 172) { hp = p - 116 + 1;  wp = 0;        }
    else              { hp = p - 172 + 1;  wp = 57;       }
    float4* d = (float4*)&g_xpad[((size_t)(b * HP + hp) * WP + wp) * CI];
    d[threadIdx.x] = make_float4(0.f, 0.f, 0.f, 0.f);
}

// NCHW -> padded NHWC (full fp32; rounding happens after the 3-sums)
__global__ void transpose_kernel(const float* __restrict__ x) {
    __shared__ float t[32][57];
    const int h = blockIdx.x, icb = blockIdx.y, b = blockIdx.z, tid = threadIdx.x;
    for (int i = tid; i < 32 * 56; i += 256) {
        int ic_l = i / 56, w = i % 56;
        t[ic_l][w] = x[((size_t)(b * CI + icb * 32 + ic_l) * HH + h) * WW + w];
    }
    __syncthreads();
    for (int i = tid; i < 56 * 32; i += 256) {
        int w = i / 32, ic_l = i % 32;
        g_xpad[((size_t)(b * HP + h + 1) * WP + (w + 1)) * CI + icb * 32 + ic_l] = t[ic_l][w];
    }
}

// vsum[b][h][wp][ic] = sum_{d=0..2} xpad[b][h+d][wp][ic], tf32-rounded
__global__ void vsum_kernel() {
    const int h = blockIdx.x, b = blockIdx.y;
    const float4* r0 = (const float4*)&g_xpad[((size_t)(b * HP + h    ) * WP) * CI];
    const float4* r1 = (const float4*)&g_xpad[((size_t)(b * HP + h + 1) * WP) * CI];
    const float4* r2 = (const float4*)&g_xpad[((size_t)(b * HP + h + 2) * WP) * CI];
    float4* dst = (float4*)&g_vsum[((size_t)(b * HH + h) * WP) * CI];
    for (int i = threadIdx.x; i < WP * CI / 4; i += blockDim.x) {
        float4 a = r0[i], c = r1[i], e = r2[i];
        float4 o;
        o.x = tf32r(a.x + c.x + e.x);
        o.y = tf32r(a.y + c.y + e.y);
        o.z = tf32r(a.z + c.z + e.z);
        o.w = tf32r(a.w + c.w + e.w);
        dst[i] = o;
    }
}

// hsum[b][hp][w][ic] = sum_{d=0..2} xpad[b][hp][w+d][ic], tf32-rounded
__global__ void hsum_kernel() {
    const int hp = blockIdx.x, b = blockIdx.y;
    const float4* row = (const float4*)&g_xpad[((size_t)(b * HP + hp) * WP) * CI];
    float4* dst = (float4*)&g_hsum[((size_t)(b * HP + hp) * WW) * CI];
    const int C4 = CI / 4;
    for (int i = threadIdx.x; i < WW * C4; i += blockDim.x) {
        int w = i / C4, q = i % C4;
        float4 a = row[(w    ) * C4 + q];
        float4 c = row[(w + 1) * C4 + q];
        float4 e = row[(w + 2) * C4 + q];
        float4 o;
        o.x = tf32r(a.x + c.x + e.x);
        o.y = tf32r(a.y + c.y + e.y);
        o.z = tf32r(a.z + c.z + e.z);
        o.w = tf32r(a.w + c.w + e.w);
        dst[i] = o;
    }
}

// weff[o][g*128+i]: g 0..2 -> krow[o,i,s=g] (pairs vsum); g 3..5 -> kcol[o,i,r=g-3] (pairs hsum)
__global__ void weff_kernel(const float* __restrict__ w) {
    int idx = blockIdx.x * blockDim.x + threadIdx.x;
    if (idx >= CO * CI) return;
    int o = idx / CI, i = idx % CI;
    const float* wp = w + (size_t)(o * CI + i) * 9;
    float v[9];
#pragma unroll
    for (int t = 0; t < 9; ++t) v[t] = wp[t];
#pragma unroll
    for (int j = 0; j < 3; ++j) {
        float krow = v[j * 3 + 0] + v[j * 3 + 1] + v[j * 3 + 2];   // row j over columns
        float kcol = v[0 * 3 + j] + v[1 * 3 + j] + v[2 * 3 + j];   // column j over rows
        g_weff[(size_t)o * KTOT2 + (j    ) * 128 + i] = tf32r(krow);
        g_weff[(size_t)o * KTOT2 + (j + 3) * 128 + i] = tf32r(kcol);
    }
}

// ---------------------------------------------------------------------------
// Main kernel: CTA tile 128x256 (full N), 8 warps of 64x64, 4-stage cp.async
// grid = 784, block = 256, 1 CTA/SM, ILP-driven
// ---------------------------------------------------------------------------
__global__ __launch_bounds__(256, 1)
void conv_mma_kernel(const float* __restrict__ bias, float* __restrict__ y) {
    extern __shared__ char smem[];
    const uint32_t sb = smem_u32(smem);

    const int tid  = threadIdx.x;
    const int lane = tid & 31;
    const int wid  = tid >> 5;
    const int m0   = blockIdx.x * 128;

    // ---- A staging identity: row rloc (0..127), 4 segments starting at aseg0 ----
    const int rloc  = tid & 127;
    const int aseg0 = (tid >> 7) * 4;
    const int m_g   = m0 + rloc;
    const int b_s   = m_g / HW;
    const int hw_s  = m_g % HW;
    const int h_s   = hw_s / WW;
    const int w_s   = hw_s % WW;
    const float* vbase = g_vsum + (((size_t)(b_s * HH + h_s) * WP) + w_s) * CI;
    const float* hbase = g_hsum + (((size_t)(b_s * HP + h_s) * WW) + w_s) * CI;
    const int rpA = rloc & 7;

    // ---- B staging identity: row tid (0..255), all 8 segments ----
    const float* bSrc0 = g_weff + (size_t)tid * KTOT2;
    const int rpB = tid & 7;

    ((float*)(smem + OFF_BIAS))[tid] = bias[tid];

    // ---- ldmatrix lane geometry ----
    const int t   = lane >> 3;
    const int rin = lane & 7;
    const int m0w = (wid & 1) * 64;
    const int n0w = (wid >> 1) * 64;
    const int thalfA = t >> 1;
    uint32_t offA[4]; int permA[4];
#pragma unroll
    for (int mt = 0; mt < 4; ++mt) {
        int row = m0w + mt * 16 + (t & 1) * 8 + rin;
        offA[mt] = (uint32_t)row * 128;
        permA[mt] = row & 7;
    }
    const int segBoff = t & 1;
    uint32_t offB[4]; int permB[4];
#pragma unroll
    for (int p = 0; p < 4; ++p) {
        int row = n0w + p * 16 + (t >> 1) * 8 + rin;
        offB[p] = (uint32_t)row * 128 + OFF_B_STAGE;
        permB[p] = row & 7;
    }

    float acc[4][8][4];
#pragma unroll
    for (int mt = 0; mt < 4; ++mt)
#pragma unroll
        for (int nt = 0; nt < 8; ++nt)
#pragma unroll
            for (int e = 0; e < 4; ++e) acc[mt][nt][e] = 0.f;

    // ---- staging helper: group g = c>>2 selects vsum (g<3) or hsum (g>=3) ----
    auto stage = [&](int c) {
        const int st  = c % STAGES;
        const int g   = c >> 2;
        const int icq = c & 3;
        const float* ap = (g < 3)
            ? vbase + (size_t)g * CI + icq * 32
            : hbase + (size_t)(g - 3) * WW * CI + icq * 32;
        const float* bp = bSrc0 + c * 32;
        const uint32_t sA = sb + st * STAGE_BYTES + (uint32_t)rloc * 128;
        const uint32_t sB = sb + st * STAGE_BYTES + OFF_B_STAGE + (uint32_t)tid * 128;
#pragma unroll
        for (int j = 0; j < 4; ++j) {
            const int s = aseg0 + j;
            cp16(sA + (uint32_t)((s ^ rpA) << 4), ap + s * 4);
        }
#pragma unroll
        for (int s = 0; s < 8; ++s)
            cp16(sB + (uint32_t)((s ^ rpB) << 4), bp + s * 4);
    };

    stage(0); CP_COMMIT();
    stage(1); CP_COMMIT();
    stage(2); CP_COMMIT();

    for (int c = 0; c < NCHUNKS; ++c) {
        CP_WAIT2();
        __syncthreads();

        if (c + 3 < NCHUNKS) stage(c + 3);
        CP_COMMIT();

        const uint32_t stBase = sb + (c % STAGES) * STAGE_BYTES;
#pragma unroll
        for (int ks = 0; ks < 4; ++ks) {
            uint32_t af[16], bf[16];
#pragma unroll
            for (int mt = 0; mt < 4; ++mt)
                ldsm4(&af[mt * 4],
                      stBase + offA[mt] + (uint32_t)(((2 * ks + thalfA) ^ permA[mt]) << 4));
#pragma unroll
            for (int p = 0; p < 4; ++p)
                ldsm4(&bf[p * 4],
                      stBase + offB[p] + (uint32_t)(((2 * ks + segBoff) ^ permB[p]) << 4));
#pragma unroll
            for (int mt = 0; mt < 4; ++mt)
#pragma unroll
                for (int nt = 0; nt < 8; ++nt)
                    mma_tf32(acc[mt][nt], &af[mt * 4],
                             bf[(nt >> 1) * 4 + (nt & 1) * 2],
                             bf[(nt >> 1) * 4 + (nt & 1) * 2 + 1]);
        }
    }

    // ---- epilogue: scatter to NCHW + bias ----
    const int qrow = lane >> 2;
    const int qcol = lane & 3;
    const float* sbias = (const float*)(smem + OFF_BIAS);
#pragma unroll
    for (int mt = 0; mt < 4; ++mt) {
#pragma unroll
        for (int rr = 0; rr < 2; ++rr) {
            const int mg = m0 + m0w + mt * 16 + qrow + rr * 8;
            const int b  = mg / HW;
            const int hw = mg % HW;
            float* yb = y + (size_t)b * CO * HW + hw;
#pragma unroll
            for (int nt = 0; nt < 8; ++nt) {
                const int oc = n0w + nt * 8 + 2 * qcol;
                yb[(size_t)(oc    ) * HW] = acc[mt][nt][rr * 2 + 0] + sbias[oc];
                yb[(size_t)(oc + 1) * HW] = acc[mt][nt][rr * 2 + 1] + sbias[oc + 1];
            }
        }
    }
}

// ---------------------------------------------------------------------------
extern "C" void kernel_launch(void* const* d_in, const int* in_sizes, int n_in,
                              void* d_out, int out_size) {
    const float* x    = (const float*)d_in[0];
    const float* w    = (const float*)d_in[1];
    const float* bias = (const float*)d_in[2];
    float* y = (float*)d_out;

    zero_halo_kernel<<<dim3(228, BATCH), 32>>>();
    transpose_kernel<<<dim3(HH, CI / 32, BATCH), 256>>>(x);
    vsum_kernel<<<dim3(HH, BATCH), 256>>>();
    hsum_kernel<<<dim3(HP, BATCH), 256>>>();
    weff_kernel<<<(CO * CI + 255) / 256, 256>>>(w);

    cudaFuncSetAttribute(conv_mma_kernel,
                         cudaFuncAttributeMaxDynamicSharedMemorySize, SMEM_TOTAL);
    conv_mma_kernel<<<BATCH * HW / 128, 256, SMEM_TOTAL>>>(bias, y);
}

// round 16
// speedup vs baseline: 2.0607x; 1.7754x over previous
#include <cuda_runtime.h>
#include <cuda_fp16.h>
#include <cstdint>

#define BATCH 32
#define CI    128
#define CO    256
#define HH    56
#define WW    56
#define HP    58
#define WP    58
#define KTOT2 768           // 6 groups x 128 ic
#define NCHUNKS 12          // KTOT2 / 64 (64 fp16 k-elems per chunk)
#define HW    (HH * WW)     // 3136

#define STAGES      3
#define STAGE_BYTES 32768       // A 16KB (128 rows x 128B) + B 16KB
#define OFF_B_STAGE 16384
#define OFF_BIAS    (STAGES * STAGE_BYTES)
#define SMEM_TOTAL  (STAGES * STAGE_BYTES + 512)

__device__ float  g_xpad[BATCH * HP * WP * CI];   // NHWC, zero halo, full fp32
__device__ __half g_vsum[BATCH * HH * WP * CI];   // vertical 3-sum, fp16
__device__ __half g_hsum[BATCH * HP * WW * CI];   // horizontal 3-sum, fp16
__device__ __half g_weff[CO * KTOT2];             // [oc][g*128+ic] = krow|kcol, fp16

__device__ __forceinline__ uint32_t smem_u32(const void* p) {
    uint32_t a;
    asm("{ .reg .u64 t; cvta.to.shared.u64 t, %1; cvt.u32.u64 %0, t; }" : "=r"(a) : "l"(p));
    return a;
}
// fp16 mma: m16n8k16, A row-major (4 regs), B col-major (2 regs), f32 accum
__device__ __forceinline__ void mma_f16(float* d, const uint32_t* a, uint32_t b0, uint32_t b1) {
    asm volatile(
        "mma.sync.aligned.m16n8k16.row.col.f32.f16.f16.f32 "
        "{%0,%1,%2,%3}, {%4,%5,%6,%7}, {%8,%9}, {%0,%1,%2,%3};"
        : "+f"(d[0]), "+f"(d[1]), "+f"(d[2]), "+f"(d[3])
        : "r"(a[0]), "r"(a[1]), "r"(a[2]), "r"(a[3]), "r"(b0), "r"(b1));
}
__device__ __forceinline__ void ldsm4(uint32_t* r, uint32_t addr) {
    asm volatile("ldmatrix.sync.aligned.m8n8.x4.shared.b16 {%0,%1,%2,%3}, [%4];"
        : "=r"(r[0]), "=r"(r[1]), "=r"(r[2]), "=r"(r[3]) : "r"(addr));
}
__device__ __forceinline__ void cp16(uint32_t saddr, const void* g) {
    asm volatile("cp.async.cg.shared.global [%0], [%1], 16;"
        :: "r"(saddr), "l"(__cvta_generic_to_global(g)) : "memory");
}
#define CP_COMMIT() asm volatile("cp.async.commit_group;" ::: "memory")
#define CP_WAIT1()  asm volatile("cp.async.wait_group 1;" ::: "memory")

// ---------------------------------------------------------------------------
// Prep kernels
// ---------------------------------------------------------------------------
// Zero only the halo of xpad (rows hp=0,57; cols wp=0,57). grid (228, BATCH), block 32.
__global__ void zero_halo_kernel() {
    const int p = blockIdx.x, b = blockIdx.y;
    int hp, wp;
    if      (p < 58)  { hp = 0;            wp = p;        }
    else if (p < 116) { hp = 57;           wp = p - 58;   }
    else if (p < 172) { hp = p - 116 + 1;  wp = 0;        }
    else              { hp = p - 172 + 1;  wp = 57;       }
    float4* d = (float4*)&g_xpad[((size_t)(b * HP + hp) * WP + wp) * CI];
    d[threadIdx.x] = make_float4(0.f, 0.f, 0.f, 0.f);
}

// NCHW -> padded NHWC (full fp32; rounding to fp16 happens after the 3-sums)
__global__ void transpose_kernel(const float* __restrict__ x) {
    __shared__ float t[32][57];
    const int h = blockIdx.x, icb = blockIdx.y, b = blockIdx.z, tid = threadIdx.x;
    for (int i = tid; i < 32 * 56; i += 256) {
        int ic_l = i / 56, w = i % 56;
        t[ic_l][w] = x[((size_t)(b * CI + icb * 32 + ic_l) * HH + h) * WW + w];
    }
    __syncthreads();
    for (int i = tid; i < 56 * 32; i += 256) {
        int w = i / 32, ic_l = i % 32;
        g_xpad[((size_t)(b * HP + h + 1) * WP + (w + 1)) * CI + icb * 32 + ic_l] = t[ic_l][w];
    }
}

// vsum[b][h][wp][ic] = fp16(sum_{d=0..2} xpad[b][h+d][wp][ic]) (fp32 sum, one rounding)
__global__ void vsum_kernel() {
    const int h = blockIdx.x, b = blockIdx.y;
    const float4* r0 = (const float4*)&g_xpad[((size_t)(b * HP + h    ) * WP) * CI];
    const float4* r1 = (const float4*)&g_xpad[((size_t)(b * HP + h + 1) * WP) * CI];
    const float4* r2 = (const float4*)&g_xpad[((size_t)(b * HP + h + 2) * WP) * CI];
    __half2* dst = (__half2*)&g_vsum[((size_t)(b * HH + h) * WP) * CI];
    for (int i = threadIdx.x; i < WP * CI / 4; i += blockDim.x) {
        float4 a = r0[i], c = r1[i], e = r2[i];
        dst[i * 2 + 0] = __floats2half2_rn(a.x + c.x + e.x, a.y + c.y + e.y);
        dst[i * 2 + 1] = __floats2half2_rn(a.z + c.z + e.z, a.w + c.w + e.w);
    }
}

// hsum[b][hp][w][ic] = fp16(sum_{d=0..2} xpad[b][hp][w+d][ic])
__global__ void hsum_kernel() {
    const int hp = blockIdx.x, b = blockIdx.y;
    const float4* row = (const float4*)&g_xpad[((size_t)(b * HP + hp) * WP) * CI];
    __half2* dst = (__half2*)&g_hsum[((size_t)(b * HP + hp) * WW) * CI];
    const int C4 = CI / 4;
    for (int i = threadIdx.x; i < WW * C4; i += blockDim.x) {
        int w = i / C4, q = i % C4;
        float4 a = row[(w    ) * C4 + q];
        float4 c = row[(w + 1) * C4 + q];
        float4 e = row[(w + 2) * C4 + q];
        dst[i * 2 + 0] = __floats2half2_rn(a.x + c.x + e.x, a.y + c.y + e.y);
        dst[i * 2 + 1] = __floats2half2_rn(a.z + c.z + e.z, a.w + c.w + e.w);
    }
}

// weff[o][g*128+i]: g 0..2 -> krow[o,i,s=g] (pairs vsum); g 3..5 -> kcol[o,i,r=g-3] (pairs hsum)
__global__ void weff_kernel(const float* __restrict__ w) {
    int idx = blockIdx.x * blockDim.x + threadIdx.x;
    if (idx >= CO * CI) return;
    int o = idx / CI, i = idx % CI;
    const float* wp = w + (size_t)(o * CI + i) * 9;
    float v[9];
#pragma unroll
    for (int t = 0; t < 9; ++t) v[t] = wp[t];
#pragma unroll
    for (int j = 0; j < 3; ++j) {
        float krow = v[j * 3 + 0] + v[j * 3 + 1] + v[j * 3 + 2];   // row j over columns
        float kcol = v[0 * 3 + j] + v[1 * 3 + j] + v[2 * 3 + j];   // column j over rows
        g_weff[(size_t)o * KTOT2 + (j    ) * 128 + i] = __float2half_rn(krow);
        g_weff[(size_t)o * KTOT2 + (j + 3) * 128 + i] = __float2half_rn(kcol);
    }
}

// ---------------------------------------------------------------------------
// Main kernel: fp16 m16n8k16, cp.async 3-stage + ldmatrix + swizzled smem
// K = 768 fp16 in 12 chunks of 64 (128B rows). CTA 128x128, 8 warps of 64x32.
// grid = (784, 2), block = 256, 2 CTAs/SM
// ---------------------------------------------------------------------------
__global__ __launch_bounds__(256, 2)
void conv_mma_kernel(const float* __restrict__ bias, float* __restrict__ y) {
    extern __shared__ char smem[];
    const uint32_t sb = smem_u32(smem);

    const int tid  = threadIdx.x;
    const int lane = tid & 31;
    const int wid  = tid >> 5;
    const int m0   = blockIdx.x * 128;
    const int n0   = blockIdx.y * 128;

    // ---- staging identity: row rloc (0..127), 4 segments starting at 4*half ----
    const int rloc = tid & 127;
    const int half = tid >> 7;
    const int m_g  = m0 + rloc;
    const int b_s  = m_g / HW;
    const int hw_s = m_g % HW;
    const int h_s  = hw_s / WW;
    const int w_s  = hw_s % WW;
    const __half* vbase = g_vsum + (((size_t)(b_s * HH + h_s) * WP) + w_s) * CI;
    const __half* hbase = g_hsum + (((size_t)(b_s * HP + h_s) * WW) + w_s) * CI;
    const __half* bSrc0 = g_weff + (size_t)(n0 + rloc) * KTOT2;
    const uint32_t rowOff = (uint32_t)rloc * 128;
    const int rp = rloc & 7;

    if (tid < 128) ((float*)(smem + OFF_BIAS))[tid] = bias[n0 + tid];

    // ---- ldmatrix lane geometry (identical structure to verified tf32 version) ----
    const int t   = lane >> 3;
    const int rin = lane & 7;
    const int m0w = (wid & 1) * 64;
    const int n0w = (wid >> 1) * 32;
    const int thalfA = t >> 1;      // A k-segment sub-index
    uint32_t offA[4]; int permA[4];
#pragma unroll
    for (int mt = 0; mt < 4; ++mt) {
        int row = m0w + mt * 16 + (t & 1) * 8 + rin;
        offA[mt] = (uint32_t)row * 128;
        permA[mt] = row & 7;
    }
    const int segBoff = t & 1;
    uint32_t offB[2]; int permB[2];
#pragma unroll
    for (int p = 0; p < 2; ++p) {
        int row = n0w + p * 16 + (t >> 1) * 8 + rin;
        offB[p] = (uint32_t)row * 128 + OFF_B_STAGE;
        permB[p] = row & 7;
    }

    float acc[4][4][4];
#pragma unroll
    for (int mt = 0; mt < 4; ++mt)
#pragma unroll
        for (int nt = 0; nt < 4; ++nt)
#pragma unroll
            for (int e = 0; e < 4; ++e) acc[mt][nt][e] = 0.f;

    // ---- staging: chunk c (0..11) = group g = c>>1, ic-half ich = (c&1)*64 ----
    auto stage = [&](int c) {
        const int st  = c % STAGES;
        const int g   = c >> 1;
        const int ich = (c & 1) * 64;
        const __half* ap = (g < 3)
            ? vbase + (size_t)g * CI + ich
            : hbase + (size_t)(g - 3) * WW * CI + ich;
        const __half* bp = bSrc0 + c * 64;
        const uint32_t sA = sb + st * STAGE_BYTES + rowOff;
        const uint32_t sB = sA + OFF_B_STAGE;
#pragma unroll
        for (int j = 0; j < 4; ++j) {
            const int s = 4 * half + j;           // segment 0..7 (8 fp16 each)
            const uint32_t ps = (uint32_t)((s ^ rp) << 4);
            cp16(sA + ps, ap + s * 8);
            cp16(sB + ps, bp + s * 8);
        }
    };

    stage(0); CP_COMMIT();
    stage(1); CP_COMMIT();

    for (int c = 0; c < NCHUNKS; ++c) {
        CP_WAIT1();
        __syncthreads();

        if (c + 2 < NCHUNKS) stage(c + 2);
        CP_COMMIT();

        const uint32_t stBase = sb + (c % STAGES) * STAGE_BYTES;
#pragma unroll
        for (int ks = 0; ks < 4; ++ks) {          // 4 k16-steps per 64-elem chunk
            uint32_t af[16], bf[8];
#pragma unroll
            for (int mt = 0; mt < 4; ++mt)
                ldsm4(&af[mt * 4],
                      stBase + offA[mt] + (uint32_t)(((2 * ks + thalfA) ^ permA[mt]) << 4));
#pragma unroll
            for (int p = 0; p < 2; ++p)
                ldsm4(&bf[p * 4],
                      stBase + offB[p] + (uint32_t)(((2 * ks + segBoff) ^ permB[p]) << 4));
#pragma unroll
            for (int mt = 0; mt < 4; ++mt)
#pragma unroll
                for (int nt = 0; nt < 4; ++nt)
                    mma_f16(acc[mt][nt], &af[mt * 4],
                            bf[(nt >> 1) * 4 + (nt & 1) * 2],
                            bf[(nt >> 1) * 4 + (nt & 1) * 2 + 1]);
        }
    }

    // ---- epilogue: scatter to NCHW + bias ----
    const int qrow = lane >> 2;
    const int qcol = lane & 3;
    const float* sbias = (const float*)(smem + OFF_BIAS);
#pragma unroll
    for (int mt = 0; mt < 4; ++mt) {
#pragma unroll
        for (int rr = 0; rr < 2; ++rr) {
            const int mg = m0 + m0w + mt * 16 + qrow + rr * 8;
            const int b  = mg / HW;
            const int hw = mg % HW;
            float* yb = y + (size_t)b * CO * HW + hw;
#pragma unroll
            for (int nt = 0; nt < 4; ++nt) {
                const int ocl = n0w + nt * 8 + 2 * qcol;
                const int oc  = n0 + ocl;
                yb[(size_t)(oc    ) * HW] = acc[mt][nt][rr * 2 + 0] + sbias[ocl];
                yb[(size_t)(oc + 1) * HW] = acc[mt][nt][rr * 2 + 1] + sbias[ocl + 1];
            }
        }
    }
}

// ---------------------------------------------------------------------------
extern "C" void kernel_launch(void* const* d_in, const int* in_sizes, int n_in,
                              void* d_out, int out_size) {
    const float* x    = (const float*)d_in[0];
    const float* w    = (const float*)d_in[1];
    const float* bias = (const float*)d_in[2];
    float* y = (float*)d_out;

    zero_halo_kernel<<<dim3(228, BATCH), 32>>>();
    transpose_kernel<<<dim3(HH, CI / 32, BATCH), 256>>>(x);
    vsum_kernel<<<dim3(HH, BATCH), 256>>>();
    hsum_kernel<<<dim3(HP, BATCH), 256>>>();
    weff_kernel<<<(CO * CI + 255) / 256, 256>>>(w);

    cudaFuncSetAttribute(conv_mma_kernel,
                         cudaFuncAttributeMaxDynamicSharedMemorySize, SMEM_TOTAL);
    dim3 grid(BATCH * HW / 128, CO / 128);
    conv_mma_kernel<<<grid, 256, SMEM_TOTAL>>>(bias, y);
}